// round 9
// baseline (speedup 1.0000x reference)
#include <cuda_runtime.h>
#include <math.h>

#define CH 24          // b*c independent planes
#define HI 192
#define WI 192
#define NI 186         // interior rows/cols
#define NPIX (NI*NI)   // 34596
#define RINGROWS 64
#define NBLK 6         // CTAs per plane
#define WARPS 8
#define THREADS (WARPS*32)

typedef unsigned long long ull;

__device__ float  g_ring[CH * RINGROWS * WI];   // zero-padded delta rows
__device__ int    g_prog[CH * WI];              // per-row completed-column counters
__device__ float  g_part[CH * NPIX * 96];       // precomputed img-tap layer-1 partials (incl. bias)
__device__ double g_sumsq;
__device__ unsigned g_done;

__device__ __forceinline__ int ldAcqG(const int* p) {
    int v;
    asm volatile("ld.acquire.gpu.global.b32 %0, [%1];" : "=r"(v) : "l"(p) : "memory");
    return v;
}
__device__ __forceinline__ void stRelG(int* p, int v) {
    asm volatile("st.release.gpu.global.b32 [%0], %1;" :: "l"(p), "r"(v) : "memory");
}
__device__ __forceinline__ int ldAcqS(unsigned a) {
    int v;
    asm volatile("ld.acquire.cta.shared.b32 %0, [%1];" : "=r"(v) : "r"(a) : "memory");
    return v;
}
__device__ __forceinline__ void stRelS(unsigned a, int v) {
    asm volatile("st.release.cta.shared.b32 [%0], %1;" :: "r"(a), "r"(v) : "memory");
}
__device__ __forceinline__ void fma2(ull& d, ull a, ull b) {
    asm("fma.rn.f32x2 %0, %1, %2, %0;" : "+l"(d) : "l"(a), "l"(b));
}
__device__ __forceinline__ float hsum2(ull v) {
    float lo, hi;
    asm("mov.b64 {%0, %1}, %2;" : "=f"(lo), "=f"(hi) : "l"(v));
    return lo + hi;
}
__device__ __forceinline__ ull packf2(float lo, float hi) {
    ull r;
    asm("mov.b64 %0, {%1, %2};" : "=l"(r) : "f"(lo), "f"(hi));
    return r;
}
// tanh(x) = 1 - 2/(e^{2x}+1); abs err ~1e-6
__device__ __forceinline__ float ftanh(float x) {
    float e = __expf(2.0f * x);
    float r;
    asm("rcp.approx.f32 %0, %1;" : "=f"(r) : "f"(e + 1.0f));
    return fmaf(-2.0f, r, 1.0f);
}

__global__ void zero_kernel() {
    int idx = blockIdx.x * blockDim.x + threadIdx.x;
    int stride = gridDim.x * blockDim.x;
    const int n = CH * RINGROWS * WI;
    for (int i = idx; i < n; i += stride) g_ring[i] = 0.0f;
    for (int i = idx; i < CH * WI; i += stride) g_prog[i] = 0;
    if (idx == 0) { g_sumsq = 0.0; g_done = 0; }
}

// Precompute: for every interior pixel, layer-1 partial from the 24 image taps + bias.
__global__ __launch_bounds__(256)
void pre_kernel(const float* __restrict__ x,
                const float* __restrict__ W1, const float* __restrict__ B1)
{
    const int lane = threadIdx.x & 31;
    const int gw   = (blockIdx.x * blockDim.x + threadIdx.x) >> 5;
    const int nw   = (gridDim.x * blockDim.x) >> 5;

    const int m0 = lane, m1 = lane + 32, m2 = lane + 64;
    // img W1 rows 0..23, packed pairs: w[p*3+mi] = (W1[2p][m], W1[2p+1][m]), p=0..11
    ull w[36];
    #pragma unroll
    for (int p = 0; p < 12; ++p) {
        #pragma unroll
        for (int mi = 0; mi < 3; ++mi) {
            int m = lane + 32 * mi;
            w[p * 3 + mi] = packf2(__ldg(W1 + (2 * p) * 96 + m), __ldg(W1 + (2 * p + 1) * 96 + m));
        }
    }
    const float bb0 = __ldg(B1 + m0), bb1 = __ldg(B1 + m1), bb2 = __ldg(B1 + m2);

    for (int row = gw; row < CH * NI; row += nw) {
        const int ch = row / NI, i = row % NI;
        const float* base = x + ch * HI * WI;
        float* partRow = g_part + ((size_t)ch * NPIX + (size_t)i * NI) * 96;
        for (int j = 0; j < NI; ++j) {
            float tp[24];
            #pragma unroll
            for (int dy = 0; dy < 3; ++dy)
                #pragma unroll
                for (int dx = 0; dx < 7; ++dx)
                    tp[dy * 7 + dx] = __ldg(base + (i + dy) * WI + j + dx);
            #pragma unroll
            for (int dx = 0; dx < 3; ++dx)
                tp[21 + dx] = __ldg(base + (i + 3) * WI + j + dx);

            ull a0 = 0, a1 = 0, b0 = 0, b1 = 0, c0 = 0, c1 = 0;
            #pragma unroll
            for (int p = 0; p < 12; ++p) {
                ull f = packf2(tp[2 * p], tp[2 * p + 1]);
                if (p & 1) { fma2(a1, f, w[p * 3]); fma2(b1, f, w[p * 3 + 1]); fma2(c1, f, w[p * 3 + 2]); }
                else       { fma2(a0, f, w[p * 3]); fma2(b0, f, w[p * 3 + 1]); fma2(c0, f, w[p * 3 + 2]); }
            }
            float* o = partRow + j * 96;
            o[m0] = bb0 + hsum2(a0) + hsum2(a1);
            o[m1] = bb1 + hsum2(b0) + hsum2(b1);
            o[m2] = bb2 + hsum2(c0) + hsum2(c1);
        }
    }
}

__global__ __launch_bounds__(THREADS, 1)
void codec_kernel(const float* __restrict__ x,
                  const float* __restrict__ W1, const float* __restrict__ B1,
                  const float* __restrict__ W2, const float* __restrict__ B2,
                  const float* __restrict__ W3, const float* __restrict__ B3,
                  const float* __restrict__ W4, const float* __restrict__ B4,
                  float* __restrict__ out)
{
    // sW1e: early delta-tap W1 rows 24..37 as pair-packed ull[p*96+m], p=0..6
    __shared__ __align__(16) ull sW1e[7 * 96];
    // sW2q: W2 k=48..95, k-major interleaved float4 pairs
    __shared__ __align__(16) ulonglong2 sW2q[12 * 24];
    __shared__ __align__(16) ulonglong2 sW3q[6 * 12];
    __shared__ float sB2[24], sB3[12], sW4[12];
    __shared__ float sB4v;
    __shared__ __align__(16) float sH1[WARPS][96];
    __shared__ __align__(16) float sH2[WARPS][24];
    __shared__ __align__(16) float sRing[WARPS][WI];
    __shared__ int sProg[WARPS];

    const int tid = threadIdx.x;

    for (int idx = tid; idx < 7 * 96; idx += THREADS) {
        int p = idx / 96, m = idx % 96;
        sW1e[p * 96 + m] = packf2(W1[(24 + 2 * p) * 96 + m], W1[(25 + 2 * p) * 96 + m]);
    }
    {
        float* f2 = (float*)sW2q;
        for (int idx = tid; idx < 48 * 24; idx += THREADS) {
            int kk = idx / 24, m = idx % 24;
            f2[((kk >> 2) * 24 + m) * 4 + (kk & 3)] = W2[(48 + kk) * 24 + m];
        }
        float* f3 = (float*)sW3q;
        for (int idx = tid; idx < 24 * 12; idx += THREADS) {
            int k = idx / 12, m = idx % 12;
            f3[((k >> 2) * 12 + m) * 4 + (k & 3)] = W3[idx];
        }
    }
    if (tid < 24) sB2[tid] = B2[tid];
    if (tid < 12) sB3[tid] = B3[tid];
    if (tid < 12) sW4[tid] = W4[tid];
    if (tid == 0) sB4v = B4[0];
    for (int idx = tid; idx < WARPS * WI; idx += THREADS) ((float*)sRing)[idx] = 0.0f;
    if (tid < WARPS) sProg[tid] = 0;
    __syncthreads();

    const int ch   = blockIdx.x / NBLK;
    const int blk  = blockIdx.x % NBLK;
    const int w    = tid >> 5;
    const int lane = tid & 31;

    const float* xch    = x + ch * HI * WI;
    float*       ringCh = g_ring + ch * RINGROWS * WI;
    int*         progCh = g_prog + ch * WI;
    const float* partCh = g_part + (size_t)ch * NPIX * 96;

    const unsigned sprogAddr = (unsigned)__cvta_generic_to_shared(&sProg[0]);
    const unsigned sprogOwn  = sprogAddr + w * 4;
    const unsigned sprogPrev = sprogAddr + (w - 1) * 4;

    float* h1w = sH1[w];
    float* h2w = sH2[w];

    const int m0 = lane, m1 = lane + 32, m2 = lane + 64;
    const float b2l = (lane < 24) ? sB2[lane] : 0.0f;
    const float b3l = (lane < 12) ? sB3[lane] : 0.0f;
    const float w4l = (lane < 12) ? sW4[lane] : 0.0f;
    const float b4v = sB4v;

    // late W1 (rows 38..47): 15 ull in regs
    ull w1L[15];
    #pragma unroll
    for (int p = 0; p < 5; ++p)
        #pragma unroll
        for (int mi = 0; mi < 3; ++mi) {
            int m = lane + 32 * mi;
            w1L[p * 3 + mi] = packf2(__ldg(W1 + (38 + 2 * p) * 96 + m),
                                     __ldg(W1 + (39 + 2 * p) * 96 + m));
        }
    // W2 k=0..47 in regs: 24 ull (lanes 0..23 meaningful)
    ull w2r[24];
    {
        const int l24 = (lane < 24) ? lane : 0;
        #pragma unroll
        for (int k4 = 0; k4 < 12; ++k4) {
            int k = 4 * k4;
            w2r[k4 * 2 + 0] = packf2(__ldg(W2 + (k + 0) * 24 + l24), __ldg(W2 + (k + 1) * 24 + l24));
            w2r[k4 * 2 + 1] = packf2(__ldg(W2 + (k + 2) * 24 + l24), __ldg(W2 + (k + 3) * 24 + l24));
        }
    }

    double sumsqd = 0.0;

    for (int i = WARPS * blk + w; i < NI; i += NBLK * WARPS) {
        const float* ring3 = (w >= 3) ? &sRing[w - 3][0]
                                      : ringCh + ((unsigned)(i - 3) & (RINGROWS - 1)) * WI;
        const float* ring2 = (w >= 2) ? &sRing[w - 2][0]
                                      : ringCh + ((unsigned)(i - 2) & (RINGROWS - 1)) * WI;
        const float* ring1 = (w >= 1) ? &sRing[w - 1][0]
                                      : ringCh + ((unsigned)(i - 1) & (RINGROWS - 1)) * WI;
        const bool g3 = (w < 3), g2 = (w < 2), g1 = (w < 1);

        int c1 = NI + 8, c2 = NI + 8, c3 = NI + 8;
        const int *gp1 = nullptr, *gp2 = nullptr, *gp3 = nullptr;
        if (w == 0) {
            if (i - 1 >= 0) { gp1 = progCh + (i - 1); c1 = 0; }
            if (i - 2 >= 0) { gp2 = progCh + (i - 2); c2 = 0; }
            if (i - 3 >= 0) { gp3 = progCh + (i - 3); c3 = 0; }
        }
        const int  sNeedBase = (i - 1) * 256;
        const int  rowTag    = i * 256;
        int*       progMe    = progCh + i;
        float*     ringW     = ringCh + ((unsigned)i & (RINGROWS - 1)) * WI;
        const float* tgtRow  = xch + (i + 3) * WI + 3;
        const float* partRow = partCh + (size_t)i * NI * 96;
        const bool pubG      = (w >= WARPS - 3);

        int   spc = 0;
        float d0 = 0.0f, d1 = 0.0f, d2 = 0.0f;
        float rowsum = 0.0f;
        ull e00 = 0, e01 = 0, e10 = 0, e11 = 0, e20 = 0, e21 = 0;
        float pp0 = 0.0f, pp1 = 0.0f, pp2 = 0.0f;

        for (int j = 0; j < NI; ++j) {
            int nd  = j + 4; if (nd  > NI) nd  = NI;
            int nd5 = j + 5; if (nd5 > NI) nd5 = NI;
            if (w) {
                int sneed = sNeedBase + nd;
                while (spc < sneed) spc = ldAcqS(sprogPrev);
            } else {
                while (c1 < nd)  c1 = ldAcqG(gp1);
                while (c2 < nd5) c2 = ldAcqG(gp2);
                while (c3 < nd5) c3 = ldAcqG(gp3);
            }

            // ---- first iteration: do the prefetch for j=0 in place ----
            if (j == 0) {
                float ea[7], eb[7];
                #pragma unroll
                for (int t = 0; t < 7; ++t) {
                    ea[t] = g3 ? __ldcg(ring3 + t) : ring3[t];
                    eb[t] = g2 ? __ldcg(ring2 + t) : ring2[t];
                }
                ull fp[7];
                fp[0] = packf2(ea[0], ea[1]); fp[1] = packf2(ea[2], ea[3]);
                fp[2] = packf2(ea[4], ea[5]); fp[3] = packf2(ea[6], eb[0]);
                fp[4] = packf2(eb[1], eb[2]); fp[5] = packf2(eb[3], eb[4]);
                fp[6] = packf2(eb[5], eb[6]);
                #pragma unroll
                for (int p = 0; p < 7; ++p) {
                    ull wa = sW1e[p * 96 + m0], wb = sW1e[p * 96 + m1], wc = sW1e[p * 96 + m2];
                    if (p & 1) { fma2(e01, fp[p], wa); fma2(e11, fp[p], wb); fma2(e21, fp[p], wc); }
                    else       { fma2(e00, fp[p], wa); fma2(e10, fp[p], wb); fma2(e20, fp[p], wc); }
                }
                pp0 = __ldg(partRow + m0); pp1 = __ldg(partRow + m1); pp2 = __ldg(partRow + m2);
            }

            // ---- late features: row i-1 taps + own last-3 deltas ----
            float f0, f1v, f2v, f3v, f4v, f5v, f6v;
            if (g1) {
                f0  = __ldcg(ring1 + j);     f1v = __ldcg(ring1 + j + 1);
                f2v = __ldcg(ring1 + j + 2); f3v = __ldcg(ring1 + j + 3);
                f4v = __ldcg(ring1 + j + 4); f5v = __ldcg(ring1 + j + 5);
                f6v = __ldcg(ring1 + j + 6);
            } else {
                f0  = ring1[j];     f1v = ring1[j + 1];
                f2v = ring1[j + 2]; f3v = ring1[j + 3];
                f4v = ring1[j + 4]; f5v = ring1[j + 5];
                f6v = ring1[j + 6];
            }
            float tgt = __ldg(tgtRow + j);

            ull va = packf2(f0, f1v), vb = packf2(f2v, f3v), vc = packf2(f4v, f5v);
            ull vd = packf2(f6v, d0), ve = packf2(d1, d2);
            fma2(e00, va, w1L[0]);  fma2(e10, va, w1L[1]);  fma2(e20, va, w1L[2]);
            fma2(e01, vb, w1L[3]);  fma2(e11, vb, w1L[4]);  fma2(e21, vb, w1L[5]);
            fma2(e00, vc, w1L[6]);  fma2(e10, vc, w1L[7]);  fma2(e20, vc, w1L[8]);
            fma2(e01, vd, w1L[9]);  fma2(e11, vd, w1L[10]); fma2(e21, vd, w1L[11]);
            fma2(e00, ve, w1L[12]); fma2(e10, ve, w1L[13]); fma2(e20, ve, w1L[14]);
            h1w[m0] = ftanh(pp0 + hsum2(e00) + hsum2(e01));
            h1w[m1] = ftanh(pp1 + hsum2(e10) + hsum2(e11));
            h1w[m2] = ftanh(pp2 + hsum2(e20) + hsum2(e21));
            __syncwarp();

            // ---- layer 2: k<48 reg weights, k>=48 shared ----
            if (lane < 24) {
                ull a0 = 0, a1 = 0, a2 = 0, a3 = 0;
                const ulonglong2* H = (const ulonglong2*)h1w;
                #pragma unroll
                for (int k4 = 0; k4 < 12; k4 += 2) {
                    ulonglong2 h = H[k4];
                    fma2(a0, h.x, w2r[2 * k4]);      fma2(a1, h.y, w2r[2 * k4 + 1]);
                    ulonglong2 h2 = H[k4 + 1];
                    fma2(a2, h2.x, w2r[2 * k4 + 2]); fma2(a3, h2.y, w2r[2 * k4 + 3]);
                }
                #pragma unroll
                for (int k4 = 12; k4 < 24; k4 += 2) {
                    ulonglong2 h  = H[k4];
                    ulonglong2 wv = sW2q[(k4 - 12) * 24 + lane];
                    fma2(a0, h.x, wv.x); fma2(a1, h.y, wv.y);
                    ulonglong2 h2  = H[k4 + 1];
                    ulonglong2 wv2 = sW2q[(k4 - 11) * 24 + lane];
                    fma2(a2, h2.x, wv2.x); fma2(a3, h2.y, wv2.y);
                }
                float v = b2l + (hsum2(a0) + hsum2(a1)) + (hsum2(a2) + hsum2(a3));
                h2w[lane] = ftanh(v);
            }
            __syncwarp();

            // ---- layer 3 + 4 ----
            float pr = 0.0f;
            if (lane < 12) {
                ull a0 = 0, a1 = 0;
                const ulonglong2* H3 = (const ulonglong2*)h2w;
                #pragma unroll
                for (int k4 = 0; k4 < 6; ++k4) {
                    ulonglong2 h  = H3[k4];
                    ulonglong2 wv = sW3q[k4 * 12 + lane];
                    fma2(a0, h.x, wv.x); fma2(a1, h.y, wv.y);
                }
                pr = ftanh(b3l + hsum2(a0) + hsum2(a1)) * w4l;
            }
            pr += __shfl_xor_sync(0xffffffffu, pr, 16);
            pr += __shfl_xor_sync(0xffffffffu, pr, 8);
            pr += __shfl_xor_sync(0xffffffffu, pr, 4);
            pr += __shfl_xor_sync(0xffffffffu, pr, 2);
            pr += __shfl_xor_sync(0xffffffffu, pr, 1);

            float out_v = ftanh(pr + b4v);
            float delta = tgt - out_v;
            d0 = d1; d1 = d2; d2 = delta;

            if (lane == 0) {
                rowsum = fmaf(delta, delta, rowsum);
                sRing[w][3 + j] = delta;
                stRelS(sprogOwn, rowTag + j + 1);
                if (pubG) {
                    ringW[3 + j] = delta;
                    stRelG(progMe, j + 1);
                }
            }
            __syncwarp();

            // ---- off-chain prefetch for pixel j+1 ----
            if (j + 1 < NI) {
                int jj = j + 1;
                float ea[7], eb[7];
                #pragma unroll
                for (int t = 0; t < 7; ++t) {
                    ea[t] = g3 ? __ldcg(ring3 + jj + t) : ring3[jj + t];
                    eb[t] = g2 ? __ldcg(ring2 + jj + t) : ring2[jj + t];
                }
                ull fp[7];
                fp[0] = packf2(ea[0], ea[1]); fp[1] = packf2(ea[2], ea[3]);
                fp[2] = packf2(ea[4], ea[5]); fp[3] = packf2(ea[6], eb[0]);
                fp[4] = packf2(eb[1], eb[2]); fp[5] = packf2(eb[3], eb[4]);
                fp[6] = packf2(eb[5], eb[6]);
                e00 = 0; e01 = 0; e10 = 0; e11 = 0; e20 = 0; e21 = 0;
                #pragma unroll
                for (int p = 0; p < 7; ++p) {
                    ull wa = sW1e[p * 96 + m0], wb = sW1e[p * 96 + m1], wc = sW1e[p * 96 + m2];
                    if (p & 1) { fma2(e01, fp[p], wa); fma2(e11, fp[p], wb); fma2(e21, fp[p], wc); }
                    else       { fma2(e00, fp[p], wa); fma2(e10, fp[p], wb); fma2(e20, fp[p], wc); }
                }
                pp0 = __ldg(partRow + jj * 96 + m0);
                pp1 = __ldg(partRow + jj * 96 + m1);
                pp2 = __ldg(partRow + jj * 96 + m2);
            }
        }
        if (lane == 0) sumsqd += (double)rowsum;
    }
    if (lane == 0) atomicAdd(&g_sumsq, sumsqd);

    __syncthreads();
    if (tid == 0) {
        __threadfence();
        unsigned prev = atomicAdd(&g_done, 1u);
        if (prev == (unsigned)(CH * NBLK - 1)) {
            __threadfence();
            double s = *((volatile double*)&g_sumsq);
            out[0] = (float)sqrt(s / 875520.0);   // b*c*(h-2)*w = 8*3*190*192
        }
    }
}

extern "C" void kernel_launch(void* const* d_in, const int* in_sizes, int n_in,
                              void* d_out, int out_size) {
    const float* x  = (const float*)d_in[0];
    const float* W1 = (const float*)d_in[1];
    const float* b1 = (const float*)d_in[2];
    const float* W2 = (const float*)d_in[3];
    const float* b2 = (const float*)d_in[4];
    const float* W3 = (const float*)d_in[5];
    const float* b3 = (const float*)d_in[6];
    const float* W4 = (const float*)d_in[7];
    const float* b4 = (const float*)d_in[8];

    zero_kernel<<<512, 256>>>();
    pre_kernel<<<144, 256>>>(x, W1, b1);
    codec_kernel<<<CH * NBLK, THREADS>>>(x, W1, b1, W2, b2, W3, b3, W4, b4, (float*)d_out);
}

// round 10
// speedup vs baseline: 1.0928x; 1.0928x over previous
#include <cuda_runtime.h>
#include <math.h>

#define CH 24          // b*c independent planes
#define HI 192
#define WI 192
#define NI 186         // interior rows/cols
#define RINGROWS 64
#define NBLK 6         // CTAs per plane
#define WARPS 8
#define THREADS (WARPS*32)

typedef unsigned long long ull;

__device__ float  g_ring[CH * RINGROWS * WI];   // zero-padded delta rows (rows w>=5 published)
__device__ int    g_prog[CH * WI];              // per-row completed-column counters
__device__ double g_sumsq;
__device__ unsigned g_done;

__device__ __forceinline__ int ldAcqG(const int* p) {
    int v;
    asm volatile("ld.acquire.gpu.global.b32 %0, [%1];" : "=r"(v) : "l"(p) : "memory");
    return v;
}
__device__ __forceinline__ void stRelG(int* p, int v) {
    asm volatile("st.release.gpu.global.b32 [%0], %1;" :: "l"(p), "r"(v) : "memory");
}
__device__ __forceinline__ int ldAcqS(unsigned a) {
    int v;
    asm volatile("ld.acquire.cta.shared.b32 %0, [%1];" : "=r"(v) : "r"(a) : "memory");
    return v;
}
__device__ __forceinline__ void stRelS(unsigned a, int v) {
    asm volatile("st.release.cta.shared.b32 [%0], %1;" :: "r"(a), "r"(v) : "memory");
}
__device__ __forceinline__ void fma2(ull& d, ull a, ull b) {
    asm("fma.rn.f32x2 %0, %1, %2, %0;" : "+l"(d) : "l"(a), "l"(b));
}
__device__ __forceinline__ float hsum2(ull v) {
    float lo, hi;
    asm("mov.b64 {%0, %1}, %2;" : "=f"(lo), "=f"(hi) : "l"(v));
    return lo + hi;
}
__device__ __forceinline__ ull packf2(float lo, float hi) {
    ull r;
    asm("mov.b64 %0, {%1, %2};" : "=l"(r) : "f"(lo), "f"(hi));
    return r;
}
// tanh(x) = 1 - 2/(e^{2x}+1); abs err ~1e-6
__device__ __forceinline__ float ftanh(float x) {
    float e = __expf(2.0f * x);
    float r;
    asm("rcp.approx.f32 %0, %1;" : "=f"(r) : "f"(e + 1.0f));
    return fmaf(-2.0f, r, 1.0f);
}

__global__ void zero_kernel() {
    int idx = blockIdx.x * blockDim.x + threadIdx.x;
    int stride = gridDim.x * blockDim.x;
    const int n = CH * RINGROWS * WI;
    for (int i = idx; i < n; i += stride) g_ring[i] = 0.0f;
    for (int i = idx; i < CH * WI; i += stride) g_prog[i] = 0;
    if (idx == 0) { g_sumsq = 0.0; g_done = 0; }
}

__global__ __launch_bounds__(THREADS, 1)
void codec_kernel(const float* __restrict__ x,
                  const float* __restrict__ W1, const float* __restrict__ B1,
                  const float* __restrict__ W2, const float* __restrict__ B2,
                  const float* __restrict__ W3, const float* __restrict__ B3,
                  const float* __restrict__ W4, const float* __restrict__ B4,
                  float* __restrict__ out)
{
    // W1 rows 0..37 (early feats) k-major interleaved in shared (rows 38,39 zero-pad);
    // W1 rows 38..47 (late) in regs; W2 k<48 in regs, k>=48 in shared; W3 shared.
    __shared__ __align__(16) ulonglong2 sW1q[10 * 96];
    __shared__ __align__(16) ulonglong2 sW2q[12 * 24];
    __shared__ __align__(16) ulonglong2 sW3q[6 * 12];
    __shared__ float sB1[96], sB2[24], sB3[12], sW4[12];
    __shared__ float sB4v;
    __shared__ __align__(16) float sFeatE[WARPS][40];  // early feats 0..37 (+2 zero pad)
    __shared__ __align__(16) float sH1[WARPS][96];
    __shared__ __align__(16) float sH2[WARPS][24];
    __shared__ __align__(16) float sRing[WARPS][WI];
    __shared__ int sProg[WARPS];

    const int tid = threadIdx.x;

    {
        float* f1 = (float*)sW1q;
        for (int idx = tid; idx < 40 * 96; idx += THREADS) {
            int k = idx / 96, m = idx % 96;
            f1[((k >> 2) * 96 + m) * 4 + (k & 3)] = (k < 38) ? W1[k * 96 + m] : 0.0f;
        }
        float* f2 = (float*)sW2q;
        for (int idx = tid; idx < 48 * 24; idx += THREADS) {
            int kk = idx / 24, m = idx % 24;
            f2[((kk >> 2) * 24 + m) * 4 + (kk & 3)] = W2[(48 + kk) * 24 + m];
        }
        float* f3 = (float*)sW3q;
        for (int idx = tid; idx < 24 * 12; idx += THREADS) {
            int k = idx / 12, m = idx % 12;
            f3[((k >> 2) * 12 + m) * 4 + (k & 3)] = W3[idx];
        }
    }
    if (tid < 96) sB1[tid] = B1[tid];
    if (tid < 24) sB2[tid] = B2[tid];
    if (tid < 12) sB3[tid] = B3[tid];
    if (tid < 12) sW4[tid] = W4[tid];
    if (tid == 0) sB4v = B4[0];
    for (int idx = tid; idx < WARPS * WI; idx += THREADS) ((float*)sRing)[idx] = 0.0f;
    for (int idx = tid; idx < WARPS * 40; idx += THREADS) ((float*)sFeatE)[idx] = 0.0f;
    if (tid < WARPS) sProg[tid] = 0;
    __syncthreads();

    const int ch   = blockIdx.x / NBLK;
    const int blk  = blockIdx.x % NBLK;
    const int w    = tid >> 5;
    const int lane = tid & 31;

    const float* xch    = x + ch * HI * WI;
    float*       ringCh = g_ring + ch * RINGROWS * WI;
    int*         progCh = g_prog + ch * WI;

    const unsigned sprogAddr = (unsigned)__cvta_generic_to_shared(&sProg[0]);
    const unsigned sprogOwn  = sprogAddr + w * 4;
    const unsigned sprogPrev = sprogAddr + (w - 1) * 4;

    float* featE = sFeatE[w];
    float* h1w   = sH1[w];
    float* h2w   = sH2[w];

    const int m0 = lane, m1 = lane + 32, m2 = lane + 64;
    const float bb0 = sB1[m0], bb1 = sB1[m1], bb2 = sB1[m2];
    const float b2l = (lane < 24) ? sB2[lane] : 0.0f;
    const float b3l = (lane < 12) ? sB3[lane] : 0.0f;
    const float w4l = (lane < 12) ? sW4[lane] : 0.0f;
    const float b4v = sB4v;

    // late W1 (rows 38..47): 15 ull in regs
    ull w1L[15];
    #pragma unroll
    for (int p = 0; p < 5; ++p)
        #pragma unroll
        for (int mi = 0; mi < 3; ++mi) {
            int m = lane + 32 * mi;
            w1L[p * 3 + mi] = packf2(__ldg(W1 + (38 + 2 * p) * 96 + m),
                                     __ldg(W1 + (39 + 2 * p) * 96 + m));
        }
    // W2 k=0..47 in regs: 24 ull (lanes 0..23 meaningful)
    ull w2r[24];
    {
        const int l24 = (lane < 24) ? lane : 0;
        #pragma unroll
        for (int k4 = 0; k4 < 12; ++k4) {
            int k = 4 * k4;
            w2r[k4 * 2 + 0] = packf2(__ldg(W2 + (k + 0) * 24 + l24), __ldg(W2 + (k + 1) * 24 + l24));
            w2r[k4 * 2 + 1] = packf2(__ldg(W2 + (k + 2) * 24 + l24), __ldg(W2 + (k + 3) * 24 + l24));
        }
    }

    double sumsqd = 0.0;

    for (int i = WARPS * blk + w; i < NI; i += NBLK * WARPS) {
        // early-tap lane sources: lanes 0..20 img dy=lane/7 dx=lane%7; 21..23 img row3 dx=lane-21;
        // 24..30 ring(i-3) dx=lane-24; 31 ring(i-2) dx=0; second pass lanes 0..5 ring(i-2) dx=lane+1
        const float* ring3 = (w >= 3) ? &sRing[w - 3][0]
                                      : ringCh + ((unsigned)(i - 3) & (RINGROWS - 1)) * WI;
        const float* ring2 = (w >= 2) ? &sRing[w - 2][0]
                                      : ringCh + ((unsigned)(i - 2) & (RINGROWS - 1)) * WI;
        const float* ring1 = (w >= 1) ? &sRing[w - 1][0]
                                      : ringCh + ((unsigned)(i - 1) & (RINGROWS - 1)) * WI;
        const bool g3 = (w < 3), g2 = (w < 2), g1 = (w < 1);

        const float* eb1;
        const bool eb1img = (lane < 24);
        if (lane < 21)      eb1 = xch + (i + lane / 7) * WI + (lane % 7);
        else if (lane < 24) eb1 = xch + (i + 3) * WI + (lane - 21);
        else if (lane < 31) eb1 = ring3 + (lane - 24);
        else                eb1 = ring2;
        const bool eb1g = (!eb1img) && ((lane < 31) ? g3 : g2);
        const float* eb2 = ring2 + lane + 1;   // lanes 0..5

        int c1 = NI + 8, c2 = NI + 8, c3 = NI + 8;
        const int *gp1 = nullptr, *gp2 = nullptr, *gp3 = nullptr;
        if (w == 0) {
            if (i - 1 >= 0) { gp1 = progCh + (i - 1); c1 = 0; }
            if (i - 2 >= 0) { gp2 = progCh + (i - 2); c2 = 0; }
            if (i - 3 >= 0) { gp3 = progCh + (i - 3); c3 = 0; }
        }
        const int  sNeedBase = (i - 1) * 256;
        const int  rowTag    = i * 256;
        int*       progMe    = progCh + i;
        float*     ringW     = ringCh + ((unsigned)i & (RINGROWS - 1)) * WI;
        const float* tgtRow  = xch + (i + 3) * WI + 3;
        const bool pubG      = (w >= WARPS - 3);

        int   spc = 0;
        float d0 = 0.0f, d1 = 0.0f, d2 = 0.0f;
        float rowsum = 0.0f;
        ull e00 = 0, e01 = 0, e10 = 0, e11 = 0, e20 = 0, e21 = 0;
        float tgt = __ldg(tgtRow);     // prefetched target for current pixel

        for (int j = 0; j < NI; ++j) {
            int nd  = j + 4; if (nd  > NI) nd  = NI;
            int nd5 = j + 5; if (nd5 > NI) nd5 = NI;
            // ---- wavefront wait: single shared poll (w>=1) or global polls (w==0) ----
            if (w) {
                int sneed = sNeedBase + nd;
                while (spc < sneed) spc = ldAcqS(sprogPrev);
            } else {
                while (c1 < nd)  c1 = ldAcqG(gp1);
                while (c2 < nd5) c2 = ldAcqG(gp2);
                while (c3 < nd5) c3 = ldAcqG(gp3);
            }

            // ---- first iteration: build early accumulators in place ----
            if (j == 0) {
                float v = eb1g ? __ldcg(eb1) : (eb1img ? __ldg(eb1) : eb1[0]);
                featE[lane] = v;
                if (lane < 6) featE[32 + lane] = g2 ? __ldcg(eb2) : eb2[0];
                __syncwarp();
                const ulonglong2* F2 = (const ulonglong2*)featE;
                #pragma unroll
                for (int k4 = 0; k4 < 10; ++k4) {
                    ulonglong2 f  = F2[k4];
                    ulonglong2 wa = sW1q[k4 * 96 + m0];
                    ulonglong2 wb = sW1q[k4 * 96 + m1];
                    ulonglong2 wc = sW1q[k4 * 96 + m2];
                    fma2(e00, f.x, wa.x); fma2(e01, f.y, wa.y);
                    fma2(e10, f.x, wb.x); fma2(e11, f.y, wb.y);
                    fma2(e20, f.x, wc.x); fma2(e21, f.y, wc.y);
                }
            }

            // ---- late features: 7 taps of row i-1 + own last-3 deltas ----
            float f0, f1v, f2v, f3v, f4v, f5v, f6v;
            if (g1) {
                f0  = __ldcg(ring1 + j);     f1v = __ldcg(ring1 + j + 1);
                f2v = __ldcg(ring1 + j + 2); f3v = __ldcg(ring1 + j + 3);
                f4v = __ldcg(ring1 + j + 4); f5v = __ldcg(ring1 + j + 5);
                f6v = __ldcg(ring1 + j + 6);
            } else {
                f0  = ring1[j];     f1v = ring1[j + 1];
                f2v = ring1[j + 2]; f3v = ring1[j + 3];
                f4v = ring1[j + 4]; f5v = ring1[j + 5];
                f6v = ring1[j + 6];
            }

            // ---- finish layer 1 (15 FFMA2, reg weights) ----
            ull va = packf2(f0, f1v), vb = packf2(f2v, f3v), vc = packf2(f4v, f5v);
            ull vd = packf2(f6v, d0), ve = packf2(d1, d2);
            fma2(e00, va, w1L[0]);  fma2(e10, va, w1L[1]);  fma2(e20, va, w1L[2]);
            fma2(e01, vb, w1L[3]);  fma2(e11, vb, w1L[4]);  fma2(e21, vb, w1L[5]);
            fma2(e00, vc, w1L[6]);  fma2(e10, vc, w1L[7]);  fma2(e20, vc, w1L[8]);
            fma2(e01, vd, w1L[9]);  fma2(e11, vd, w1L[10]); fma2(e21, vd, w1L[11]);
            fma2(e00, ve, w1L[12]); fma2(e10, ve, w1L[13]); fma2(e20, ve, w1L[14]);
            h1w[m0] = ftanh(bb0 + hsum2(e00) + hsum2(e01));
            h1w[m1] = ftanh(bb1 + hsum2(e10) + hsum2(e11));
            h1w[m2] = ftanh(bb2 + hsum2(e20) + hsum2(e21));
            __syncwarp();

            // ---- off-chain prefetch for pixel j+1 (overlaps L2/L3 latency) ----
            float tgtN = 0.0f;
            bool doPre = (j + 1 < NI);
            if (doPre) {
                int jj = j + 1;
                float v = eb1g ? __ldcg(eb1 + jj) : (eb1img ? __ldg(eb1 + jj) : eb1[jj]);
                featE[lane] = v;
                if (lane < 6) featE[32 + lane] = g2 ? __ldcg(eb2 + jj) : eb2[jj];
                tgtN = __ldg(tgtRow + jj);
            }

            // ---- layer 2: 96 -> 24 (lanes 0..23); k<48 regs, k>=48 shared ----
            if (lane < 24) {
                ull a0 = 0, a1 = 0, a2 = 0, a3 = 0;
                const ulonglong2* H = (const ulonglong2*)h1w;
                #pragma unroll
                for (int k4 = 0; k4 < 12; k4 += 2) {
                    ulonglong2 h = H[k4];
                    fma2(a0, h.x, w2r[2 * k4]);      fma2(a1, h.y, w2r[2 * k4 + 1]);
                    ulonglong2 h2 = H[k4 + 1];
                    fma2(a2, h2.x, w2r[2 * k4 + 2]); fma2(a3, h2.y, w2r[2 * k4 + 3]);
                }
                #pragma unroll
                for (int k4 = 12; k4 < 24; k4 += 2) {
                    ulonglong2 h  = H[k4];
                    ulonglong2 wv = sW2q[(k4 - 12) * 24 + lane];
                    fma2(a0, h.x, wv.x); fma2(a1, h.y, wv.y);
                    ulonglong2 h2  = H[k4 + 1];
                    ulonglong2 wv2 = sW2q[(k4 - 11) * 24 + lane];
                    fma2(a2, h2.x, wv2.x); fma2(a3, h2.y, wv2.y);
                }
                float v = b2l + (hsum2(a0) + hsum2(a1)) + (hsum2(a2) + hsum2(a3));
                h2w[lane] = ftanh(v);
            }
            __syncwarp();

            // ---- start next pixel's early layer-1 accumulation (off-chain) ----
            ull n00 = 0, n01 = 0, n10 = 0, n11 = 0, n20 = 0, n21 = 0;
            if (doPre) {
                const ulonglong2* F2 = (const ulonglong2*)featE;
                #pragma unroll
                for (int k4 = 0; k4 < 10; ++k4) {
                    ulonglong2 f  = F2[k4];
                    ulonglong2 wa = sW1q[k4 * 96 + m0];
                    ulonglong2 wb = sW1q[k4 * 96 + m1];
                    ulonglong2 wc = sW1q[k4 * 96 + m2];
                    fma2(n00, f.x, wa.x); fma2(n01, f.y, wa.y);
                    fma2(n10, f.x, wb.x); fma2(n11, f.y, wb.y);
                    fma2(n20, f.x, wc.x); fma2(n21, f.y, wc.y);
                }
            }

            // ---- layer 3: 24 -> 12 (lanes 0..11) + layer 4 dot-12 ----
            float pr = 0.0f;
            if (lane < 12) {
                ull a0 = 0, a1 = 0;
                const ulonglong2* H3 = (const ulonglong2*)h2w;
                #pragma unroll
                for (int k4 = 0; k4 < 6; ++k4) {
                    ulonglong2 h  = H3[k4];
                    ulonglong2 wv = sW3q[k4 * 12 + lane];
                    fma2(a0, h.x, wv.x); fma2(a1, h.y, wv.y);
                }
                pr = ftanh(b3l + hsum2(a0) + hsum2(a1)) * w4l;
            }
            pr += __shfl_xor_sync(0xffffffffu, pr, 16);
            pr += __shfl_xor_sync(0xffffffffu, pr, 8);
            pr += __shfl_xor_sync(0xffffffffu, pr, 4);
            pr += __shfl_xor_sync(0xffffffffu, pr, 2);
            pr += __shfl_xor_sync(0xffffffffu, pr, 1);

            float out_v = ftanh(pr + b4v);
            float delta = tgt - out_v;            // every lane
            d0 = d1; d1 = d2; d2 = delta;
            tgt = tgtN;
            e00 = n00; e01 = n01; e10 = n10; e11 = n11; e20 = n20; e21 = n21;

            if (lane == 0) {
                rowsum = fmaf(delta, delta, rowsum);
                sRing[w][3 + j] = delta;
                stRelS(sprogOwn, rowTag + j + 1);
                if (pubG) {
                    ringW[3 + j] = delta;
                    stRelG(progMe, j + 1);
                }
            }
            __syncwarp();
        }
        if (lane == 0) sumsqd += (double)rowsum;
    }
    if (lane == 0) atomicAdd(&g_sumsq, sumsqd);

    __syncthreads();
    if (tid == 0) {
        __threadfence();
        unsigned prev = atomicAdd(&g_done, 1u);
        if (prev == (unsigned)(CH * NBLK - 1)) {
            __threadfence();
            double s = *((volatile double*)&g_sumsq);
            out[0] = (float)sqrt(s / 875520.0);   // b*c*(h-2)*w = 8*3*190*192
        }
    }
}

extern "C" void kernel_launch(void* const* d_in, const int* in_sizes, int n_in,
                              void* d_out, int out_size) {
    const float* x  = (const float*)d_in[0];
    const float* W1 = (const float*)d_in[1];
    const float* b1 = (const float*)d_in[2];
    const float* W2 = (const float*)d_in[3];
    const float* b2 = (const float*)d_in[4];
    const float* W3 = (const float*)d_in[5];
    const float* b3 = (const float*)d_in[6];
    const float* W4 = (const float*)d_in[7];
    const float* b4 = (const float*)d_in[8];

    zero_kernel<<<512, 256>>>();
    codec_kernel<<<CH * NBLK, THREADS>>>(x, W1, b1, W2, b2, W3, b3, W4, b4, (float*)d_out);
}

// round 11
// speedup vs baseline: 1.2095x; 1.1067x over previous
#include <cuda_runtime.h>
#include <math.h>

#define CH 24          // b*c independent planes
#define HI 192
#define WI 192
#define NI 186         // interior rows/cols
#define RINGROWS 64
#define NBLK 6         // CTAs per plane
#define WARPS 8
#define THREADS (WARPS*32)

typedef unsigned long long ull;

__device__ float  g_ring[CH * RINGROWS * WI];   // zero-padded delta rows (rows w>=5 published)
__device__ int    g_prog[CH * WI];              // per-row completed-column counters
__device__ double g_sumsq;
__device__ unsigned g_done;

__device__ __forceinline__ int ldAcqG(const int* p) {
    int v;
    asm volatile("ld.acquire.gpu.global.b32 %0, [%1];" : "=r"(v) : "l"(p) : "memory");
    return v;
}
__device__ __forceinline__ void stRelG(int* p, int v) {
    asm volatile("st.release.gpu.global.b32 [%0], %1;" :: "l"(p), "r"(v) : "memory");
}
__device__ __forceinline__ int ldAcqS(unsigned a) {
    int v;
    asm volatile("ld.acquire.cta.shared.b32 %0, [%1];" : "=r"(v) : "r"(a) : "memory");
    return v;
}
__device__ __forceinline__ void stRelS(unsigned a, int v) {
    asm volatile("st.release.cta.shared.b32 [%0], %1;" :: "r"(a), "r"(v) : "memory");
}
__device__ __forceinline__ void fma2(ull& d, ull a, ull b) {
    asm("fma.rn.f32x2 %0, %1, %2, %0;" : "+l"(d) : "l"(a), "l"(b));
}
__device__ __forceinline__ float hsum2(ull v) {
    float lo, hi;
    asm("mov.b64 {%0, %1}, %2;" : "=f"(lo), "=f"(hi) : "l"(v));
    return lo + hi;
}
__device__ __forceinline__ ull packf2(float lo, float hi) {
    ull r;
    asm("mov.b64 %0, {%1, %2};" : "=l"(r) : "f"(lo), "f"(hi));
    return r;
}
// tanh(x) = 1 - 2/(e^{2x}+1); abs err ~1e-6
__device__ __forceinline__ float ftanh(float x) {
    float e = __expf(2.0f * x);
    float r;
    asm("rcp.approx.f32 %0, %1;" : "=f"(r) : "f"(e + 1.0f));
    return fmaf(-2.0f, r, 1.0f);
}

__global__ void zero_kernel() {
    int idx = blockIdx.x * blockDim.x + threadIdx.x;
    int stride = gridDim.x * blockDim.x;
    const int n = CH * RINGROWS * WI;
    for (int i = idx; i < n; i += stride) g_ring[i] = 0.0f;
    for (int i = idx; i < CH * WI; i += stride) g_prog[i] = 0;
    if (idx == 0) { g_sumsq = 0.0; g_done = 0; }
}

__global__ __launch_bounds__(THREADS, 1)
void codec_kernel(const float* __restrict__ x,
                  const float* __restrict__ W1, const float* __restrict__ B1,
                  const float* __restrict__ W2, const float* __restrict__ B2,
                  const float* __restrict__ W3, const float* __restrict__ B3,
                  const float* __restrict__ W4, const float* __restrict__ B4,
                  float* __restrict__ out)
{
    // All weights staged in shared (k-major interleaved float4 pairs);
    // W1 chunks 0..7 additionally mirrored in registers (48 ull/lane).
    __shared__ __align__(16) ulonglong2 sW1q[12 * 96];
    __shared__ __align__(16) ulonglong2 sW2q[24 * 24];
    __shared__ __align__(16) ulonglong2 sW3q[6 * 12];
    __shared__ float sB1[96], sB2[24], sB3[12], sW4[12];
    __shared__ float sB4v;
    __shared__ __align__(16) float sFeat[WARPS][48];
    __shared__ __align__(16) float sH1[WARPS][96];
    __shared__ __align__(16) float sH2[WARPS][24];
    __shared__ __align__(16) float sRing[WARPS][WI];   // per-warp current row deltas
    __shared__ int sProg[WARPS];

    const int tid = threadIdx.x;

    {
        float* f1 = (float*)sW1q;
        for (int idx = tid; idx < 48 * 96; idx += THREADS) {
            int k = idx / 96, m = idx % 96;
            f1[((k >> 2) * 96 + m) * 4 + (k & 3)] = W1[idx];
        }
        float* f2 = (float*)sW2q;
        for (int idx = tid; idx < 96 * 24; idx += THREADS) {
            int k = idx / 24, m = idx % 24;
            f2[((k >> 2) * 24 + m) * 4 + (k & 3)] = W2[idx];
        }
        float* f3 = (float*)sW3q;
        for (int idx = tid; idx < 24 * 12; idx += THREADS) {
            int k = idx / 12, m = idx % 12;
            f3[((k >> 2) * 12 + m) * 4 + (k & 3)] = W3[idx];
        }
    }
    if (tid < 96) sB1[tid] = B1[tid];
    if (tid < 24) sB2[tid] = B2[tid];
    if (tid < 12) sB3[tid] = B3[tid];
    if (tid < 12) sW4[tid] = W4[tid];
    if (tid == 0) sB4v = B4[0];
    for (int idx = tid; idx < WARPS * WI; idx += THREADS) ((float*)sRing)[idx] = 0.0f;
    if (tid < WARPS) sProg[tid] = 0;
    __syncthreads();

    const int ch   = blockIdx.x / NBLK;
    const int blk  = blockIdx.x % NBLK;
    const int w    = tid >> 5;
    const int lane = tid & 31;

    const float* xch    = x + ch * HI * WI;
    float*       ringCh = g_ring + ch * RINGROWS * WI;
    int*         progCh = g_prog + ch * WI;

    const unsigned sprogAddr = (unsigned)__cvta_generic_to_shared(&sProg[0]);
    const unsigned sprogOwn  = sprogAddr + w * 4;
    const unsigned sprogPrev = sprogAddr + (w - 1) * 4;

    float* featw = sFeat[w];
    float* h1w   = sH1[w];
    float* h2w   = sH2[w];

    const int m0 = lane, m1 = lane + 32, m2 = lane + 64;
    const float bb0 = sB1[m0], bb1 = sB1[m1], bb2 = sB1[m2];
    const float b2l = (lane < 24) ? sB2[lane] : 0.0f;
    const float b3l = (lane < 12) ? sB3[lane] : 0.0f;
    const float w4l = (lane < 12) ? sW4[lane] : 0.0f;
    const float b4v = sB4v;

    // ---- W1 chunks 0..7 (k=0..31) in registers: 48 packed f32x2 per lane ----
    ull w1r[48];
    #pragma unroll
    for (int k4 = 0; k4 < 8; ++k4) {
        #pragma unroll
        for (int mi = 0; mi < 3; ++mi) {
            int m = lane + 32 * mi;
            int k = 4 * k4;
            w1r[k4 * 6 + mi * 2 + 0] = packf2(__ldg(W1 + (k + 0) * 96 + m), __ldg(W1 + (k + 1) * 96 + m));
            w1r[k4 * 6 + mi * 2 + 1] = packf2(__ldg(W1 + (k + 2) * 96 + m), __ldg(W1 + (k + 3) * 96 + m));
        }
    }

    // ---- static tap descriptors ----
    // feats 0..23: image taps; feats 24..31 (lanes 24..31): s=lane-24 -> dy = s==7 ? 1 : 0, dx;
    // feats 32..44 (lanes 0..12): s=lane+8 -> dy=s/7 (1 or 2), dx=s%7;
    // feats 45..47 (lanes 13..15): own last-3 deltas from registers.
    int p1_dy = 0, p1_dx = 0;
    if (lane >= 24) { int s = lane - 24; p1_dy = (s == 7) ? 1 : 0; p1_dx = (s == 7) ? 0 : s; }
    int p2_dy = 0, p2_dx = 0;
    if (lane < 13) { int s = lane + 8; p2_dy = s / 7; p2_dx = s % 7; }

    double sumsqd = 0.0;

    for (int i = WARPS * blk + w; i < NI; i += NBLK * WARPS) {
        const float* imgP = nullptr;
        if (lane < 21)      imgP = xch + (i + lane / 7) * WI + (lane % 7);
        else if (lane < 24) imgP = xch + (i + 3) * WI + (lane - 21);

        // tap row local index l = w-3+dy: l>=0 -> own-CTA sRing[l]; else global ring
        const float* base1 = nullptr; bool tapG1 = false;
        if (lane >= 24) {
            int l = w - 3 + p1_dy;
            if (l >= 0) base1 = &sRing[l][p1_dx];
            else { base1 = ringCh + ((unsigned)(i - 3 + p1_dy) & (RINGROWS - 1)) * WI + p1_dx; tapG1 = true; }
        }
        const float* base2 = nullptr; bool tapG2 = false;
        if (lane < 13) {
            int l = w - 3 + p2_dy;
            if (l >= 0) base2 = &sRing[l][p2_dx];
            else { base2 = ringCh + ((unsigned)(i - 3 + p2_dy) & (RINGROWS - 1)) * WI + p2_dx; tapG2 = true; }
        }

        // wavefront sync sources: single shared poll for w>=1; three global polls for w=0
        int c1 = NI + 8, c2 = NI + 8, c3 = NI + 8;
        const int *gp1 = nullptr, *gp2 = nullptr, *gp3 = nullptr;
        if (w == 0) {
            if (i - 1 >= 0) { gp1 = progCh + (i - 1); c1 = 0; }
            if (i - 2 >= 0) { gp2 = progCh + (i - 2); c2 = 0; }
            if (i - 3 >= 0) { gp3 = progCh + (i - 3); c3 = 0; }
        }
        const int  sNeedBase = (i - 1) * 256;
        const int  rowTag    = i * 256;
        int*       progMe    = progCh + i;
        float*     ringW     = ringCh + ((unsigned)i & (RINGROWS - 1)) * WI;
        const float* tgtRow  = xch + (i + 3) * WI + 3;
        const bool pubG      = (w >= WARPS - 3);

        int   spc = 0;
        float d0 = 0.0f, d1 = 0.0f, d2 = 0.0f;   // deltas j-3, j-2, j-1 (all lanes)
        float rowsum = 0.0f;

        for (int j = 0; j < NI; ++j) {
            int nd = j + 4; if (nd > NI) nd = NI;
            // ---- wavefront wait ----
            if (w) {
                int sneed = sNeedBase + nd;
                while (spc < sneed) spc = ldAcqS(sprogPrev);
            } else {
                while (c1 < nd) c1 = ldAcqG(gp1);
                while (c2 < nd) c2 = ldAcqG(gp2);
                while (c3 < nd) c3 = ldAcqG(gp3);
            }

            // ---- gather 48 features into shared staging ----
            float v1;
            if (lane < 24)  v1 = __ldg(imgP + j);
            else if (tapG1) v1 = __ldcg(base1 + j);
            else            v1 = base1[j];
            featw[lane] = v1;
            if (lane < 13)       featw[lane + 32] = tapG2 ? __ldcg(base2 + j) : base2[j];
            else if (lane < 16)  featw[lane + 32] = (lane == 13) ? d0 : (lane == 14) ? d1 : d2;
            __syncwarp();
            float tgt = __ldg(tgtRow + j);   // broadcast

            // ---- layer 1: 48 -> 96; chunks 0..7 reg weights, chunks 8..11 shared ----
            ull a00 = 0, a01 = 0, a10 = 0, a11 = 0, a20 = 0, a21 = 0;
            {
                const ulonglong2* F2 = (const ulonglong2*)featw;
                #pragma unroll
                for (int k4 = 0; k4 < 8; ++k4) {
                    ulonglong2 f = F2[k4];
                    fma2(a00, f.x, w1r[k4 * 6 + 0]); fma2(a01, f.y, w1r[k4 * 6 + 1]);
                    fma2(a10, f.x, w1r[k4 * 6 + 2]); fma2(a11, f.y, w1r[k4 * 6 + 3]);
                    fma2(a20, f.x, w1r[k4 * 6 + 4]); fma2(a21, f.y, w1r[k4 * 6 + 5]);
                }
                #pragma unroll
                for (int k4 = 8; k4 < 12; ++k4) {
                    ulonglong2 f  = F2[k4];
                    ulonglong2 wa = sW1q[k4 * 96 + m0];
                    ulonglong2 wb = sW1q[k4 * 96 + m1];
                    ulonglong2 wc = sW1q[k4 * 96 + m2];
                    fma2(a00, f.x, wa.x); fma2(a01, f.y, wa.y);
                    fma2(a10, f.x, wb.x); fma2(a11, f.y, wb.y);
                    fma2(a20, f.x, wc.x); fma2(a21, f.y, wc.y);
                }
            }
            h1w[m0] = ftanh(bb0 + hsum2(a00) + hsum2(a01));
            h1w[m1] = ftanh(bb1 + hsum2(a10) + hsum2(a11));
            h1w[m2] = ftanh(bb2 + hsum2(a20) + hsum2(a21));
            __syncwarp();

            // ---- layer 2: 96 -> 24 (lanes 0..23), shared weights ----
            if (lane < 24) {
                ull a0 = 0, a1 = 0, a2 = 0, a3 = 0;
                const ulonglong2* H = (const ulonglong2*)h1w;
                #pragma unroll
                for (int k4 = 0; k4 < 24; k4 += 2) {
                    ulonglong2 h  = H[k4];
                    ulonglong2 wv = sW2q[k4 * 24 + lane];
                    fma2(a0, h.x, wv.x); fma2(a1, h.y, wv.y);
                    ulonglong2 h2  = H[k4 + 1];
                    ulonglong2 wv2 = sW2q[(k4 + 1) * 24 + lane];
                    fma2(a2, h2.x, wv2.x); fma2(a3, h2.y, wv2.y);
                }
                float v = b2l + (hsum2(a0) + hsum2(a1)) + (hsum2(a2) + hsum2(a3));
                h2w[lane] = ftanh(v);
            }
            __syncwarp();

            // ---- layer 3: 24 -> 12 (lanes 0..11) + layer 4 dot-12 ----
            float pr = 0.0f;
            if (lane < 12) {
                ull a0 = 0, a1 = 0;
                const ulonglong2* H3 = (const ulonglong2*)h2w;
                #pragma unroll
                for (int k4 = 0; k4 < 6; ++k4) {
                    ulonglong2 h  = H3[k4];
                    ulonglong2 wv = sW3q[k4 * 12 + lane];
                    fma2(a0, h.x, wv.x); fma2(a1, h.y, wv.y);
                }
                pr = ftanh(b3l + hsum2(a0) + hsum2(a1)) * w4l;
            }
            pr += __shfl_xor_sync(0xffffffffu, pr, 16);
            pr += __shfl_xor_sync(0xffffffffu, pr, 8);
            pr += __shfl_xor_sync(0xffffffffu, pr, 4);
            pr += __shfl_xor_sync(0xffffffffu, pr, 2);
            pr += __shfl_xor_sync(0xffffffffu, pr, 1);

            float out_v = ftanh(pr + b4v);
            float delta = tgt - out_v;            // every lane computes delta
            d0 = d1; d1 = d2; d2 = delta;

            if (lane == 0) {
                rowsum = fmaf(delta, delta, rowsum);
                sRing[w][3 + j] = delta;                  // own-row ring (shared)
                stRelS(sprogOwn, rowTag + j + 1);         // local release flag
                if (pubG) {
                    ringW[3 + j] = delta;                 // global ring for next-CTA consumers
                    stRelG(progMe, j + 1);
                }
            }
            __syncwarp();
        }
        if (lane == 0) sumsqd += (double)rowsum;
    }
    if (lane == 0) atomicAdd(&g_sumsq, sumsqd);

    // ---- fused finish: last CTA writes the output ----
    __syncthreads();
    if (tid == 0) {
        __threadfence();
        unsigned prev = atomicAdd(&g_done, 1u);
        if (prev == (unsigned)(CH * NBLK - 1)) {
            __threadfence();
            double s = *((volatile double*)&g_sumsq);
            out[0] = (float)sqrt(s / 875520.0);   // b*c*(h-2)*w = 8*3*190*192
        }
    }
}

extern "C" void kernel_launch(void* const* d_in, const int* in_sizes, int n_in,
                              void* d_out, int out_size) {
    const float* x  = (const float*)d_in[0];
    const float* W1 = (const float*)d_in[1];
    const float* b1 = (const float*)d_in[2];
    const float* W2 = (const float*)d_in[3];
    const float* b2 = (const float*)d_in[4];
    const float* W3 = (const float*)d_in[5];
    const float* b3 = (const float*)d_in[6];
    const float* W4 = (const float*)d_in[7];
    const float* b4 = (const float*)d_in[8];

    zero_kernel<<<512, 256>>>();
    codec_kernel<<<CH * NBLK, THREADS>>>(x, W1, b1, W2, b2, W3, b3, W4, b4, (float*)d_out);
}